// round 4
// baseline (speedup 1.0000x reference)
#include <cuda_runtime.h>

#define BB 4
#define LL 8192
#define DD 512
#define NC 128     // chunks along L
#define CL 64      // chunk length = LL/NC
#define D4 (DD/4)  // 128 float4 channels

// Scratch (SoA): per (b, chunk, d) complex carry state. 2 * 1 MB.
__device__ float g_cr[BB * NC * DD];
__device__ float g_ci[BB * NC * DD];

// ---------------------------------------------------------------------------
// Pass 1: local scan per chunk from zero state; store end state.
// grid = (NC, BB), block = D4 = 128 threads; each thread owns 4 channels.
// ---------------------------------------------------------------------------
__global__ void lru_pass1(const float* __restrict__ x,
                          const float* __restrict__ nu,
                          const float* __restrict__ theta) {
    const int d4 = threadIdx.x;         // 0..127
    const int c  = blockIdx.x;
    const int b  = blockIdx.y;

    const float4 nu4 = ((const float4*)nu)[d4];
    const float4 th4 = ((const float4*)theta)[d4];

    float lr[4], li[4];
    {
        const float* nup = (const float*)&nu4;
        const float* thp = (const float*)&th4;
#pragma unroll
        for (int j = 0; j < 4; j++) {
            const float mag = expf(-expf(nup[j]));
            float s, co;
            sincosf(thp[j], &s, &co);
            lr[j] = mag * co;
            li[j] = mag * s;
        }
    }

    const float4* xp = (const float4*)(x + ((size_t)(b * LL + c * CL)) * DD) + d4;

    float hr[4] = {0.f, 0.f, 0.f, 0.f};
    float hi[4] = {0.f, 0.f, 0.f, 0.f};
#pragma unroll 8
    for (int i = 0; i < CL; i++) {
        const float4 xv = xp[(size_t)i * D4];
        const float* xj = (const float*)&xv;
#pragma unroll
        for (int j = 0; j < 4; j++) {
            const float nhr = fmaf(lr[j], hr[j], fmaf(-li[j], hi[j], xj[j]));
            const float nhi = fmaf(li[j], hr[j], lr[j] * hi[j]);
            hr[j] = nhr;
            hi[j] = nhi;
        }
    }

    const int cidx = (b * NC + c) * DD + 4 * d4;
    *(float4*)(g_cr + cidx) = make_float4(hr[0], hr[1], hr[2], hr[3]);
    *(float4*)(g_ci + cidx) = make_float4(hi[0], hi[1], hi[2], hi[3]);
}

// ---------------------------------------------------------------------------
// Pass 2: scan across chunks per (b,d) with multiplier lambda^CL.
// Replaces local end-states with true *incoming* states per chunk.
// ---------------------------------------------------------------------------
__global__ void lru_pass2(const float* __restrict__ nu,
                          const float* __restrict__ theta) {
    const int idx = blockIdx.x * blockDim.x + threadIdx.x;  // b*DD + d
    if (idx >= BB * DD) return;
    const int b = idx / DD;
    const int d = idx % DD;

    const float a    = expf(nu[d]);
    const float Lmag = expf(-(float)CL * a);
    float s, co;
    sincosf((float)CL * theta[d], &s, &co);
    const float Lr = Lmag * co;
    const float Li = Lmag * s;

    float* crp = g_cr + (size_t)b * NC * DD + d;
    float* cip = g_ci + (size_t)b * NC * DD + d;
    float cr = 0.f, ci = 0.f;
#pragma unroll
    for (int c = 0; c < NC; c++) {
        const float er = crp[(size_t)c * DD];
        const float ei = cip[(size_t)c * DD];
        crp[(size_t)c * DD] = cr;   // incoming state for chunk c
        cip[(size_t)c * DD] = ci;
        const float ncr = fmaf(Lr, cr, fmaf(-Li, ci, er));
        const float nci = fmaf(Li, cr, fmaf(Lr, ci, ei));
        cr = ncr;
        ci = nci;
    }
}

// ---------------------------------------------------------------------------
// Pass 3: rerun local scan seeded with true incoming state; emit outputs.
// Streaming stores so y doesn't evict x from L2 (pass1 warmed it).
// grid = (NC, BB), block = 128
// ---------------------------------------------------------------------------
__global__ void lru_pass3(const float* __restrict__ x,
                          const float* __restrict__ nu,
                          const float* __restrict__ theta,
                          const float* __restrict__ gre,
                          const float* __restrict__ gim,
                          float* __restrict__ out) {
    const int d4 = threadIdx.x;
    const int c  = blockIdx.x;
    const int b  = blockIdx.y;

    const float4 nu4 = ((const float4*)nu)[d4];
    const float4 th4 = ((const float4*)theta)[d4];
    const float4 gr4 = ((const float4*)gre)[d4];
    const float4 gi4 = ((const float4*)gim)[d4];
    const float* grj = (const float*)&gr4;
    const float* gij = (const float*)&gi4;

    float lr[4], li[4];
    {
        const float* nup = (const float*)&nu4;
        const float* thp = (const float*)&th4;
#pragma unroll
        for (int j = 0; j < 4; j++) {
            const float mag = expf(-expf(nup[j]));
            float s, co;
            sincosf(thp[j], &s, &co);
            lr[j] = mag * co;
            li[j] = mag * s;
        }
    }

    const int cidx = (b * NC + c) * DD + 4 * d4;
    const float4 h0r = *(const float4*)(g_cr + cidx);
    const float4 h0i = *(const float4*)(g_ci + cidx);
    float hr[4] = {h0r.x, h0r.y, h0r.z, h0r.w};
    float hi[4] = {h0i.x, h0i.y, h0i.z, h0i.w};

    const size_t base = ((size_t)(b * LL + c * CL)) * DD;
    const float4* xp = (const float4*)(x + base) + d4;
    float4* yp = (float4*)(out + base) + d4;

#pragma unroll 8
    for (int i = 0; i < CL; i++) {
        const float4 xv = xp[(size_t)i * D4];
        const float* xj = (const float*)&xv;
        float4 yv;
        float* yj = (float*)&yv;
#pragma unroll
        for (int j = 0; j < 4; j++) {
            const float nhr = fmaf(lr[j], hr[j], fmaf(-li[j], hi[j], xj[j]));
            const float nhi = fmaf(li[j], hr[j], lr[j] * hi[j]);
            hr[j] = nhr;
            hi[j] = nhi;
            yj[j] = fmaf(grj[j], nhr, -gij[j] * nhi);
        }
        __stcs(yp + (size_t)i * D4, yv);
    }
}

// ---------------------------------------------------------------------------
extern "C" void kernel_launch(void* const* d_in, const int* in_sizes, int n_in,
                              void* d_out, int out_size) {
    const float* x     = (const float*)d_in[0];
    const float* nu    = (const float*)d_in[1];
    const float* theta = (const float*)d_in[2];
    const float* gre   = (const float*)d_in[3];
    const float* gim   = (const float*)d_in[4];
    float* out = (float*)d_out;

    dim3 grid1(NC, BB);
    lru_pass1<<<grid1, D4>>>(x, nu, theta);
    lru_pass2<<<(BB * DD + 255) / 256, 256>>>(nu, theta);
    lru_pass3<<<grid1, D4>>>(x, nu, theta, gre, gim, out);
}